// round 2
// baseline (speedup 1.0000x reference)
#include <cuda_runtime.h>

#define B_DIM 32
#define L_DIM 4096
#define D_DIM 768
#define D4 (D_DIM / 4)   // 192 float4 per position

// Scratch for per-row SEP/EOS positions (no cudaMalloc allowed).
__device__ int g_sep[B_DIM];
__device__ int g_eos[B_DIM];

// Kernel 1: per-row first occurrence of token 4 (SEP) and token 2 (EOS).
// Handles both int32 and int64 token buffers: for int64 little-endian data
// every odd 32-bit word is 0 (tokens are in [2, 32000]); for int32 data odd
// words are real tokens >= 2. We probe 4 odd words to pick the stride.
__global__ void find_markers_kernel(const int* __restrict__ x32) {
    __shared__ int s_sep, s_eos;
    const int b = blockIdx.x;
    if (threadIdx.x == 0) { s_sep = L_DIM; s_eos = L_DIM; }
    __syncthreads();

    // dtype probe (same result in every thread; cheap L1/L2 hits)
    const bool is64 = (x32[1] == 0) & (x32[3] == 0) & (x32[5] == 0) & (x32[7] == 0);
    const int stride = is64 ? 2 : 1;
    const int* row = x32 + (long long)b * L_DIM * stride;

    int lsep = L_DIM, leos = L_DIM;
    for (int i = threadIdx.x; i < L_DIM; i += blockDim.x) {
        const int v = row[i * stride];   // low word == full token either way
        if (v == 4 && i < lsep) lsep = i;
        if (v == 2 && i < leos) leos = i;
    }
    #pragma unroll
    for (int off = 16; off > 0; off >>= 1) {
        lsep = min(lsep, __shfl_down_sync(0xFFFFFFFFu, lsep, off));
        leos = min(leos, __shfl_down_sync(0xFFFFFFFFu, leos, off));
    }
    if ((threadIdx.x & 31) == 0) {
        atomicMin(&s_sep, lsep);
        atomicMin(&s_eos, leos);
    }
    __syncthreads();
    if (threadIdx.x == 0) {
        g_sep[b] = s_sep;
        g_eos[b] = s_eos;
    }
}

// Kernel 2: out[b, l, :] = W[seg(b,l), :], one float4 store per thread.
__global__ void write_embedding_kernel(const float4* __restrict__ W4,
                                       float4* __restrict__ out) {
    const int idx = blockIdx.x * blockDim.x + threadIdx.x;  // < B*L*D4 (25.2M)
    const int p   = idx / D4;         // position index b*L + l
    const int d4  = idx - p * D4;     // float4 index within D
    const int b   = p >> 12;          // / 4096
    const int l   = p & (L_DIM - 1);  // % 4096

    const int sep = g_sep[b];
    const int eos = g_eos[b];
    const int seg = (l < sep) ? 1 : ((l < eos) ? 2 : 0);

    out[idx] = W4[seg * D4 + d4];
}

extern "C" void kernel_launch(void* const* d_in, const int* in_sizes, int n_in,
                              void* d_out, int out_size) {
    // Identify inputs by element count: x has B*L, W has 3*D.
    const int* x;
    const float* W;
    if (in_sizes[0] == B_DIM * L_DIM) {
        x = (const int*)d_in[0];
        W = (const float*)d_in[1];
    } else {
        x = (const int*)d_in[1];
        W = (const float*)d_in[0];
    }

    find_markers_kernel<<<B_DIM, 256>>>(x);

    const int total4 = B_DIM * L_DIM * D4;  // 25,165,824
    const int threads = 256;
    write_embedding_kernel<<<total4 / threads, threads>>>(
        (const float4*)W, (float4*)d_out);
}